// round 8
// baseline (speedup 1.0000x reference)
#include <cuda_runtime.h>
#include <cstdint>

#define NS 100000
#define NP 20000
#define EDGES 500000
#define H 128

// ---------------- scratch (static device globals; no allocation) ----------------
__device__ int   g_degP[NP];
__device__ int   g_degS[NS];
__device__ int   g_startP[NP];
__device__ int   g_startS[NS];
__device__ int   g_curP[NP];
__device__ int   g_curS[NS];
__device__ int   g_cnt[2];        // region allocator counters {P, S}
__device__ int   g_csrP[EDGES];   // song ids grouped (contiguously) by playlist
__device__ int   g_csrS[EDGES];   // playlist ids grouped (contiguously) by song
__device__ __align__(16) float g_xplay[(size_t)NP * H];
__device__ __align__(16) float g_aggP[(size_t)NP * H];
__device__ __align__(16) float g_aggS[(size_t)NS * H];
__device__ __align__(16) float g_p1[(size_t)NP * H];
__device__ __align__(16) float g_s1[(size_t)NS * H];

// ---------------- small utility kernels (all pointers passed explicitly) ----------------
__global__ void init_kernel(int* degS, int* degP, int* cnt) {
    int i = blockIdx.x * blockDim.x + threadIdx.x;
    if (i < NS) degS[i] = 0;
    if (i < NP) degP[i] = 0;
    if (i == 0) { cnt[0] = 0; cnt[1] = 0; }
}

__global__ void gather_xplay_kernel(const float* __restrict__ pemb,
                                    const int* __restrict__ pid,
                                    float* __restrict__ xplay) {
    int i = blockIdx.x * blockDim.x + threadIdx.x;  // over NP*32 float4s
    if (i < NP * 32) {
        int row = i >> 5;
        int c4  = i & 31;
        int srow = pid[row];
        reinterpret_cast<float4*>(xplay)[(size_t)row * 32 + c4] =
            reinterpret_cast<const float4*>(pemb)[(size_t)srow * 32 + c4];
    }
}

__global__ void count_kernel(const int* __restrict__ es, const int* __restrict__ ep,
                             int* degS, int* degP) {
    int e = blockIdx.x * blockDim.x + threadIdx.x;
    if (e < EDGES) {
        atomicAdd(&degS[es[e]], 1);
        atomicAdd(&degP[ep[e]], 1);
    }
}

// Assign each destination a contiguous region via atomic bump allocation.
// Region ORDER is arbitrary but per-destination grouping is exact.
__global__ void assign_regions_kernel(const int* degP, const int* degS,
                                      int* startP, int* startS,
                                      int* curP, int* curS, int* cnt) {
    int i = blockIdx.x * blockDim.x + threadIdx.x;
    if (i < NP) {
        int base = atomicAdd(&cnt[0], degP[i]);
        startP[i] = base;
        curP[i]   = base;
    }
    if (i < NS) {
        int base = atomicAdd(&cnt[1], degS[i]);
        startS[i] = base;
        curS[i]   = base;
    }
}

__global__ void build_csr_kernel(const int* __restrict__ es, const int* __restrict__ ep,
                                 int* curP, int* curS,
                                 int* __restrict__ csrP, int* __restrict__ csrS) {
    int e = blockIdx.x * blockDim.x + threadIdx.x;
    if (e < EDGES) {
        int s = es[e], p = ep[e];
        int slotP = atomicAdd(&curP[p], 1);
        csrP[slotP] = s;
        int slotS = atomicAdd(&curS[s], 1);
        csrS[slotS] = p;
    }
}

// ---------------- mean aggregation: one warp per destination ----------------
__global__ void aggregate_kernel(const float* __restrict__ src,
                                 const int* __restrict__ start,
                                 const int* __restrict__ deg,
                                 const int* __restrict__ csr,
                                 float* __restrict__ dst, int ndst) {
    int gw   = (blockIdx.x * blockDim.x + threadIdx.x) >> 5;
    int lane = threadIdx.x & 31;
    if (gw >= ndst) return;
    int s = start[gw];
    int cnt = deg[gw];
    float4 acc = {0.f, 0.f, 0.f, 0.f};
    for (int j = s; j < s + cnt; j++) {
        int nb = csr[j];
        float4 v = __ldg(reinterpret_cast<const float4*>(src + (size_t)nb * H) + lane);
        acc.x += v.x; acc.y += v.y; acc.z += v.z; acc.w += v.w;
    }
    float inv = (cnt > 0) ? 1.0f / (float)cnt : 0.0f;
    float4 r;
    r.x = acc.x * inv;
    r.y = acc.y * inv;
    r.z = acc.z * inv;
    r.w = acc.w * inv;
    reinterpret_cast<float4*>(dst + (size_t)gw * H)[lane] = r;
}

// ---------------- fused SAGE GEMM: out = A@W1 + B@W2 + bias (opt relu) ----------------
// A, B: [n,128]; W1, W2: [128,128] row-major (k-major); out: [n,128]
#define BM 64
#define BN 128
#define BK 16
__global__ __launch_bounds__(256) void sage_gemm_kernel(
    const float* __restrict__ A, const float* __restrict__ B,
    const float* __restrict__ W1, const float* __restrict__ W2,
    const float* __restrict__ bias, float* __restrict__ out,
    int n, int do_relu) {
    __shared__ float As[BM][BK + 1];
    __shared__ float Ws[BK][BN];

    int block_row = blockIdx.x * BM;
    int tid = threadIdx.x;
    int tx = tid & 15;   // col group: cols tx*8 .. tx*8+7
    int ty = tid >> 4;   // row group: rows ty*4 .. ty*4+3

    float acc[4][8];
    #pragma unroll
    for (int i = 0; i < 4; i++)
        #pragma unroll
        for (int jj = 0; jj < 8; jj++) acc[i][jj] = 0.f;

    #pragma unroll
    for (int pass = 0; pass < 2; pass++) {
        const float* Aop = pass ? B : A;
        const float* Wop = pass ? W2 : W1;
        for (int k0 = 0; k0 < 128; k0 += BK) {
            // load A tile: 64 rows x 16 k; one float4 per thread
            {
                int r  = tid >> 2;
                int kc = (tid & 3) * 4;
                int gr = block_row + r;
                float4 v = {0.f, 0.f, 0.f, 0.f};
                if (gr < n)
                    v = *reinterpret_cast<const float4*>(Aop + (size_t)gr * H + k0 + kc);
                As[r][kc + 0] = v.x;
                As[r][kc + 1] = v.y;
                As[r][kc + 2] = v.z;
                As[r][kc + 3] = v.w;
            }
            // load W tile: 16 x 128; two float4 per thread
            #pragma unroll
            for (int rep = 0; rep < 2; rep++) {
                int idx = tid + rep * 256;   // float4 index in [0,512)
                int r = idx >> 5;            // 32 float4 per row
                int c = (idx & 31) * 4;
                *reinterpret_cast<float4*>(&Ws[r][c]) =
                    *reinterpret_cast<const float4*>(Wop + (size_t)(k0 + r) * H + c);
            }
            __syncthreads();
            #pragma unroll
            for (int k = 0; k < BK; k++) {
                float a[4], w[8];
                #pragma unroll
                for (int i = 0; i < 4; i++) a[i] = As[ty * 4 + i][k];
                #pragma unroll
                for (int jj = 0; jj < 2; jj++) {
                    float4 wv = *reinterpret_cast<const float4*>(&Ws[k][tx * 8 + jj * 4]);
                    w[jj * 4 + 0] = wv.x; w[jj * 4 + 1] = wv.y;
                    w[jj * 4 + 2] = wv.z; w[jj * 4 + 3] = wv.w;
                }
                #pragma unroll
                for (int i = 0; i < 4; i++)
                    #pragma unroll
                    for (int jj = 0; jj < 8; jj++)
                        acc[i][jj] += a[i] * w[jj];
            }
            __syncthreads();
        }
    }

    // epilogue
    float bv[8];
    #pragma unroll
    for (int jj = 0; jj < 8; jj++) bv[jj] = bias[tx * 8 + jj];
    #pragma unroll
    for (int i = 0; i < 4; i++) {
        int gr = block_row + ty * 4 + i;
        if (gr >= n) continue;
        float4 o0, o1;
        float v0 = acc[i][0] + bv[0], v1 = acc[i][1] + bv[1];
        float v2 = acc[i][2] + bv[2], v3 = acc[i][3] + bv[3];
        float v4 = acc[i][4] + bv[4], v5 = acc[i][5] + bv[5];
        float v6 = acc[i][6] + bv[6], v7 = acc[i][7] + bv[7];
        if (do_relu) {
            v0 = fmaxf(v0, 0.f); v1 = fmaxf(v1, 0.f); v2 = fmaxf(v2, 0.f); v3 = fmaxf(v3, 0.f);
            v4 = fmaxf(v4, 0.f); v5 = fmaxf(v5, 0.f); v6 = fmaxf(v6, 0.f); v7 = fmaxf(v7, 0.f);
        }
        o0.x = v0; o0.y = v1; o0.z = v2; o0.w = v3;
        o1.x = v4; o1.y = v5; o1.z = v6; o1.w = v7;
        float* orow = out + (size_t)gr * H + tx * 8;
        *reinterpret_cast<float4*>(orow)     = o0;
        *reinterpret_cast<float4*>(orow + 4) = o1;
    }
}

// ---------------- host launcher ----------------
extern "C" void kernel_launch(void* const* d_in, const int* in_sizes, int n_in,
                              void* d_out, int out_size) {
    const float* song_x  = (const float*)d_in[0];
    const int*   pid     = (const int*)d_in[1];
    const int*   e_song  = (const int*)d_in[2];
    const int*   e_play  = (const int*)d_in[3];
    const float* pemb    = (const float*)d_in[4];
    const float* Wl1_sp  = (const float*)d_in[5];
    const float* Wr1_sp  = (const float*)d_in[6];
    const float* b1_sp   = (const float*)d_in[7];
    const float* Wl1_ps  = (const float*)d_in[8];
    const float* Wr1_ps  = (const float*)d_in[9];
    const float* b1_ps   = (const float*)d_in[10];
    const float* Wl2_sp  = (const float*)d_in[11];
    const float* Wr2_sp  = (const float*)d_in[12];
    const float* b2_sp   = (const float*)d_in[13];
    const float* Wl2_ps  = (const float*)d_in[14];
    const float* Wr2_ps  = (const float*)d_in[15];
    const float* b2_ps   = (const float*)d_in[16];

    float* out_s2 = (float*)d_out;                       // [NS, H]
    float* out_p2 = (float*)d_out + (size_t)NS * H;      // [NP, H]

    // Resolve DEVICE addresses of the scratch symbols. Passing a __device__
    // array by name from host code yields the host shadow symbol (which GB300's
    // ATS happily dereferences into host .bss — the round-2..6 bug).
    int *degP, *degS, *startP, *startS, *curP, *curS, *cnt, *csrP, *csrS;
    float *xplay, *aggP, *aggS, *p1, *s1;
    cudaGetSymbolAddress((void**)&degP,   g_degP);
    cudaGetSymbolAddress((void**)&degS,   g_degS);
    cudaGetSymbolAddress((void**)&startP, g_startP);
    cudaGetSymbolAddress((void**)&startS, g_startS);
    cudaGetSymbolAddress((void**)&curP,   g_curP);
    cudaGetSymbolAddress((void**)&curS,   g_curS);
    cudaGetSymbolAddress((void**)&cnt,    g_cnt);
    cudaGetSymbolAddress((void**)&csrP,   g_csrP);
    cudaGetSymbolAddress((void**)&csrS,   g_csrS);
    cudaGetSymbolAddress((void**)&xplay,  g_xplay);
    cudaGetSymbolAddress((void**)&aggP,   g_aggP);
    cudaGetSymbolAddress((void**)&aggS,   g_aggS);
    cudaGetSymbolAddress((void**)&p1,     g_p1);
    cudaGetSymbolAddress((void**)&s1,     g_s1);

    // graph structure (rebuilt every call; deterministic work)
    init_kernel<<<(NS + 255) / 256, 256>>>(degS, degP, cnt);
    gather_xplay_kernel<<<(NP * 32 + 255) / 256, 256>>>(pemb, pid, xplay);
    count_kernel<<<(EDGES + 255) / 256, 256>>>(e_song, e_play, degS, degP);
    assign_regions_kernel<<<(NS + 255) / 256, 256>>>(degP, degS, startP, startS, curP, curS, cnt);
    build_csr_kernel<<<(EDGES + 255) / 256, 256>>>(e_song, e_play, curP, curS, csrP, csrS);

    // layer 1
    aggregate_kernel<<<(NP * 32 + 255) / 256, 256>>>(song_x, startP, degP, csrP, aggP, NP);
    aggregate_kernel<<<(NS * 32 + 255) / 256, 256>>>(xplay, startS, degS, csrS, aggS, NS);
    sage_gemm_kernel<<<(NP + BM - 1) / BM, 256>>>(aggP, xplay, Wl1_sp, Wr1_sp, b1_sp, p1, NP, 1);
    sage_gemm_kernel<<<(NS + BM - 1) / BM, 256>>>(aggS, song_x, Wl1_ps, Wr1_ps, b1_ps, s1, NS, 1);

    // layer 2
    aggregate_kernel<<<(NP * 32 + 255) / 256, 256>>>(s1, startP, degP, csrP, aggP, NP);
    aggregate_kernel<<<(NS * 32 + 255) / 256, 256>>>(p1, startS, degS, csrS, aggS, NS);
    sage_gemm_kernel<<<(NP + BM - 1) / BM, 256>>>(aggP, p1, Wl2_sp, Wr2_sp, b2_sp, out_p2, NP, 0);
    sage_gemm_kernel<<<(NS + BM - 1) / BM, 256>>>(aggS, s1, Wl2_ps, Wr2_ps, b2_ps, out_s2, NS, 0);
}

// round 10
// speedup vs baseline: 2.2148x; 2.2148x over previous
#include <cuda_runtime.h>
#include <cstdint>

#define NS 100000
#define NP 20000
#define EDGES 500000
#define H 128

// ---------------- scratch (static device globals; no allocation) ----------------
__device__ int   g_degP[NP];
__device__ int   g_degS[NS];
__device__ int   g_startP[NP];
__device__ int   g_startS[NS];
__device__ int   g_curP[NP];
__device__ int   g_curS[NS];
__device__ int   g_cnt[2];        // region allocator counters {P, S}
__device__ int   g_csrP[EDGES];   // song ids grouped (contiguously) by playlist
__device__ int   g_csrS[EDGES];   // playlist ids grouped (contiguously) by song
__device__ __align__(16) float g_xplay[(size_t)NP * H];
__device__ __align__(16) float g_aggP[(size_t)NP * H];
__device__ __align__(16) float g_aggS[(size_t)NS * H];
__device__ __align__(16) float g_p1[(size_t)NP * H];
__device__ __align__(16) float g_s1[(size_t)NS * H];

// ---------------- small utility kernels ----------------
__global__ void init_kernel(int* degS, int* degP, int* cnt) {
    int i = blockIdx.x * blockDim.x + threadIdx.x;
    if (i < NS) degS[i] = 0;
    if (i < NP) degP[i] = 0;
    if (i == 0) { cnt[0] = 0; cnt[1] = 0; }
}

__global__ void gather_xplay_kernel(const float* __restrict__ pemb,
                                    const int* __restrict__ pid,
                                    float* __restrict__ xplay) {
    int i = blockIdx.x * blockDim.x + threadIdx.x;  // over NP*32 float4s
    if (i < NP * 32) {
        int row = i >> 5;
        int c4  = i & 31;
        int srow = pid[row];
        reinterpret_cast<float4*>(xplay)[(size_t)row * 32 + c4] =
            reinterpret_cast<const float4*>(pemb)[(size_t)srow * 32 + c4];
    }
}

__global__ void count_kernel(const int* __restrict__ es, const int* __restrict__ ep,
                             int* degS, int* degP) {
    int e = blockIdx.x * blockDim.x + threadIdx.x;
    if (e < EDGES) {
        atomicAdd(&degS[es[e]], 1);
        atomicAdd(&degP[ep[e]], 1);
    }
}

// Assign each destination a contiguous region via atomic bump allocation.
__global__ void assign_regions_kernel(const int* degP, const int* degS,
                                      int* startP, int* startS,
                                      int* curP, int* curS, int* cnt) {
    int i = blockIdx.x * blockDim.x + threadIdx.x;
    if (i < NP) {
        int base = atomicAdd(&cnt[0], degP[i]);
        startP[i] = base;
        curP[i]   = base;
    }
    if (i < NS) {
        int base = atomicAdd(&cnt[1], degS[i]);
        startS[i] = base;
        curS[i]   = base;
    }
}

__global__ void build_csr_kernel(const int* __restrict__ es, const int* __restrict__ ep,
                                 int* curP, int* curS,
                                 int* __restrict__ csrP, int* __restrict__ csrS) {
    int e = blockIdx.x * blockDim.x + threadIdx.x;
    if (e < EDGES) {
        int s = es[e], p = ep[e];
        int slotP = atomicAdd(&curP[p], 1);
        csrP[slotP] = s;
        int slotS = atomicAdd(&curS[s], 1);
        csrS[slotS] = p;
    }
}

// ---------------- mean aggregation: one warp per destination ----------------
__global__ void aggregate_kernel(const float* __restrict__ src,
                                 const int* __restrict__ start,
                                 const int* __restrict__ deg,
                                 const int* __restrict__ csr,
                                 float* __restrict__ dst, int ndst) {
    int gw   = (blockIdx.x * blockDim.x + threadIdx.x) >> 5;
    int lane = threadIdx.x & 31;
    if (gw >= ndst) return;
    int s = start[gw];
    int cnt = deg[gw];
    float4 acc = {0.f, 0.f, 0.f, 0.f};
    for (int j = s; j < s + cnt; j++) {
        int nb = csr[j];
        float4 v = __ldg(reinterpret_cast<const float4*>(src + (size_t)nb * H) + lane);
        acc.x += v.x; acc.y += v.y; acc.z += v.z; acc.w += v.w;
    }
    float inv = (cnt > 0) ? 1.0f / (float)cnt : 0.0f;
    float4 r;
    r.x = acc.x * inv; r.y = acc.y * inv; r.z = acc.z * inv; r.w = acc.w * inv;
    reinterpret_cast<float4*>(dst + (size_t)gw * H)[lane] = r;
}

// ---------------- tensor-core fused SAGE GEMM (tf32 mma.sync) ----------------
// out = A@W1 + B@W2 + bias (opt relu).  A,B: [n,128]; W1,W2: [128,128]; out: [n,128]
// Block tile 128x128, BK=32; 8 warps in 4(m) x 2(n); warp tile 32x64 = 2x8 m16n8k8.
#define TBM 128
#define TBK 32
#define AS_STRIDE 36    // words per A row (32 + 4 pad): frag LDS hits 32 distinct banks
#define WS_STRIDE 136   // words per W row (128 + 8 pad): frag LDS hits 32 distinct banks

__device__ __forceinline__ uint32_t f2tf(float f) {
    uint32_t u;
    asm("cvt.rna.tf32.f32 %0, %1;" : "=r"(u) : "f"(f));
    return u;
}

#define MMA_TF32(C, a0, a1, a2, a3, b0, b1)                                     \
    asm volatile("mma.sync.aligned.m16n8k8.row.col.f32.tf32.tf32.f32 "          \
                 "{%0,%1,%2,%3}, {%4,%5,%6,%7}, {%8,%9}, {%0,%1,%2,%3};"        \
                 : "+f"(C[0]), "+f"(C[1]), "+f"(C[2]), "+f"(C[3])               \
                 : "r"(a0), "r"(a1), "r"(a2), "r"(a3), "r"(b0), "r"(b1))

__global__ __launch_bounds__(256) void sage_gemm_tc(
    const float* __restrict__ A, const float* __restrict__ Bm,
    const float* __restrict__ W1, const float* __restrict__ W2,
    const float* __restrict__ bias, float* __restrict__ out,
    int n, int do_relu) {
    __shared__ uint32_t As[TBM * AS_STRIDE];   // 128 x 32 tf32
    __shared__ uint32_t Ws[TBK * WS_STRIDE];   // 32 x 128 tf32

    int tid  = threadIdx.x;
    int lane = tid & 31;
    int warp = tid >> 5;
    int warp_m = warp & 3;    // 0..3 : 32 rows each
    int warp_n = warp >> 2;   // 0..1 : 64 cols each
    int block_row = blockIdx.x * TBM;
    int qid  = lane >> 2;     // groupID 0..7
    int qtid = lane & 3;      // threadID-in-group 0..3

    float c[2][8][4];
    #pragma unroll
    for (int mt = 0; mt < 2; mt++)
        #pragma unroll
        for (int nt = 0; nt < 8; nt++)
            #pragma unroll
            for (int i = 0; i < 4; i++) c[mt][nt][i] = 0.f;

    #pragma unroll
    for (int pass = 0; pass < 2; pass++) {
        const float* Aop = pass ? Bm : A;
        const float* Wop = pass ? W2 : W1;
        #pragma unroll
        for (int kc = 0; kc < 4; kc++) {
            int k0 = kc * TBK;
            // stage A tile: 128 rows x 32 k (1024 float4, 4 per thread)
            #pragma unroll
            for (int i = 0; i < 4; i++) {
                int idx = tid + i * 256;
                int r   = idx >> 3;
                int c4  = idx & 7;
                int gr  = block_row + r;
                float4 v = {0.f, 0.f, 0.f, 0.f};
                if (gr < n)
                    v = *reinterpret_cast<const float4*>(Aop + (size_t)gr * H + k0 + c4 * 4);
                uint32_t* d = &As[r * AS_STRIDE + c4 * 4];
                d[0] = f2tf(v.x); d[1] = f2tf(v.y); d[2] = f2tf(v.z); d[3] = f2tf(v.w);
            }
            // stage W tile: 32 k x 128 cols (1024 float4, 4 per thread)
            #pragma unroll
            for (int i = 0; i < 4; i++) {
                int idx = tid + i * 256;
                int r   = idx >> 5;
                int c4  = idx & 31;
                float4 v = *reinterpret_cast<const float4*>(Wop + (size_t)(k0 + r) * H + c4 * 4);
                uint32_t* d = &Ws[r * WS_STRIDE + c4 * 4];
                d[0] = f2tf(v.x); d[1] = f2tf(v.y); d[2] = f2tf(v.z); d[3] = f2tf(v.w);
            }
            __syncthreads();
            #pragma unroll
            for (int ks = 0; ks < 4; ks++) {
                int kk = ks * 8;
                uint32_t a[2][4];
                #pragma unroll
                for (int mt = 0; mt < 2; mt++) {
                    int r = warp_m * 32 + mt * 16 + qid;
                    a[mt][0] = As[r * AS_STRIDE + kk + qtid];
                    a[mt][1] = As[(r + 8) * AS_STRIDE + kk + qtid];
                    a[mt][2] = As[r * AS_STRIDE + kk + qtid + 4];
                    a[mt][3] = As[(r + 8) * AS_STRIDE + kk + qtid + 4];
                }
                #pragma unroll
                for (int nt = 0; nt < 8; nt++) {
                    int col = warp_n * 64 + nt * 8 + qid;
                    uint32_t b0 = Ws[(kk + qtid) * WS_STRIDE + col];
                    uint32_t b1 = Ws[(kk + qtid + 4) * WS_STRIDE + col];
                    MMA_TF32(c[0][nt], a[0][0], a[0][1], a[0][2], a[0][3], b0, b1);
                    MMA_TF32(c[1][nt], a[1][0], a[1][1], a[1][2], a[1][3], b0, b1);
                }
            }
            __syncthreads();
        }
    }

    // epilogue: bias (+relu), write float2 per c-pair
    #pragma unroll
    for (int mt = 0; mt < 2; mt++) {
        #pragma unroll
        for (int half = 0; half < 2; half++) {
            int r = block_row + warp_m * 32 + mt * 16 + qid + half * 8;
            if (r >= n) continue;
            float* orow = out + (size_t)r * H;
            #pragma unroll
            for (int nt = 0; nt < 8; nt++) {
                int col = warp_n * 64 + nt * 8 + qtid * 2;
                float v0 = c[mt][nt][half * 2 + 0] + __ldg(bias + col);
                float v1 = c[mt][nt][half * 2 + 1] + __ldg(bias + col + 1);
                if (do_relu) { v0 = fmaxf(v0, 0.f); v1 = fmaxf(v1, 0.f); }
                float2 o; o.x = v0; o.y = v1;
                *reinterpret_cast<float2*>(orow + col) = o;
            }
        }
    }
}

// ---------------- host launcher ----------------
extern "C" void kernel_launch(void* const* d_in, const int* in_sizes, int n_in,
                              void* d_out, int out_size) {
    const float* song_x  = (const float*)d_in[0];
    const int*   pid     = (const int*)d_in[1];
    const int*   e_song  = (const int*)d_in[2];
    const int*   e_play  = (const int*)d_in[3];
    const float* pemb    = (const float*)d_in[4];
    const float* Wl1_sp  = (const float*)d_in[5];
    const float* Wr1_sp  = (const float*)d_in[6];
    const float* b1_sp   = (const float*)d_in[7];
    const float* Wl1_ps  = (const float*)d_in[8];
    const float* Wr1_ps  = (const float*)d_in[9];
    const float* b1_ps   = (const float*)d_in[10];
    const float* Wl2_sp  = (const float*)d_in[11];
    const float* Wr2_sp  = (const float*)d_in[12];
    const float* b2_sp   = (const float*)d_in[13];
    const float* Wl2_ps  = (const float*)d_in[14];
    const float* Wr2_ps  = (const float*)d_in[15];
    const float* b2_ps   = (const float*)d_in[16];

    float* out_s2 = (float*)d_out;                       // [NS, H]
    float* out_p2 = (float*)d_out + (size_t)NS * H;      // [NP, H]

    // Resolve DEVICE addresses of scratch symbols (host shadow symbol trap).
    int *degP, *degS, *startP, *startS, *curP, *curS, *cnt, *csrP, *csrS;
    float *xplay, *aggP, *aggS, *p1, *s1;
    cudaGetSymbolAddress((void**)&degP,   g_degP);
    cudaGetSymbolAddress((void**)&degS,   g_degS);
    cudaGetSymbolAddress((void**)&startP, g_startP);
    cudaGetSymbolAddress((void**)&startS, g_startS);
    cudaGetSymbolAddress((void**)&curP,   g_curP);
    cudaGetSymbolAddress((void**)&curS,   g_curS);
    cudaGetSymbolAddress((void**)&cnt,    g_cnt);
    cudaGetSymbolAddress((void**)&csrP,   g_csrP);
    cudaGetSymbolAddress((void**)&csrS,   g_csrS);
    cudaGetSymbolAddress((void**)&xplay,  g_xplay);
    cudaGetSymbolAddress((void**)&aggP,   g_aggP);
    cudaGetSymbolAddress((void**)&aggS,   g_aggS);
    cudaGetSymbolAddress((void**)&p1,     g_p1);
    cudaGetSymbolAddress((void**)&s1,     g_s1);

    // graph structure (rebuilt every call; deterministic work)
    init_kernel<<<(NS + 255) / 256, 256>>>(degS, degP, cnt);
    gather_xplay_kernel<<<(NP * 32 + 255) / 256, 256>>>(pemb, pid, xplay);
    count_kernel<<<(EDGES + 255) / 256, 256>>>(e_song, e_play, degS, degP);
    assign_regions_kernel<<<(NS + 255) / 256, 256>>>(degP, degS, startP, startS, curP, curS, cnt);
    build_csr_kernel<<<(EDGES + 255) / 256, 256>>>(e_song, e_play, curP, curS, csrP, csrS);

    // layer 1
    aggregate_kernel<<<(NP * 32 + 255) / 256, 256>>>(song_x, startP, degP, csrP, aggP, NP);
    aggregate_kernel<<<(NS * 32 + 255) / 256, 256>>>(xplay, startS, degS, csrS, aggS, NS);
    sage_gemm_tc<<<(NP + TBM - 1) / TBM, 256>>>(aggP, xplay, Wl1_sp, Wr1_sp, b1_sp, p1, NP, 1);
    sage_gemm_tc<<<(NS + TBM - 1) / TBM, 256>>>(aggS, song_x, Wl1_ps, Wr1_ps, b1_ps, s1, NS, 1);

    // layer 2
    aggregate_kernel<<<(NP * 32 + 255) / 256, 256>>>(s1, startP, degP, csrP, aggP, NP);
    aggregate_kernel<<<(NS * 32 + 255) / 256, 256>>>(p1, startS, degS, csrS, aggS, NS);
    sage_gemm_tc<<<(NP + TBM - 1) / TBM, 256>>>(aggP, p1, Wl2_sp, Wr2_sp, b2_sp, out_p2, NP, 0);
    sage_gemm_tc<<<(NS + TBM - 1) / TBM, 256>>>(aggS, s1, Wl2_ps, Wr2_ps, b2_ps, out_s2, NS, 0);
}